// round 16
// baseline (speedup 1.0000x reference)
#include <cuda_runtime.h>
#include <cuda_bf16.h>
#include <math.h>
#include <stdint.h>

typedef unsigned long long ull;

// ---------------- problem constants ----------------
#define T_STEPS 600
#define BATCH   64
#define HID     40
#define IN_F    257
#define NTOK    (BATCH * T_STEPS)   // 38400
#define G3H     120
#define TWOH    80
#define KX_PAD  320
#define KF_PAD  768

// ---------------- scratch ----------------
__device__ float g_giF[(size_t)T_STEPS * BATCH * G3H];
__device__ float g_giB[(size_t)T_STEPS * BATCH * G3H];
__device__ float g_hcat[(size_t)NTOK * TWOH];
__device__ __nv_bfloat16 g_xhi[(size_t)NTOK * KX_PAD];
__device__ __nv_bfloat16 g_xlo[(size_t)NTOK * KX_PAD];
__device__ __nv_bfloat16 g_fhi[(size_t)NTOK * KF_PAD];
__device__ __nv_bfloat16 g_flo[(size_t)NTOK * KF_PAD];
__device__ __nv_bfloat16 g_Wgh[2 * G3H * KX_PAD];
__device__ __nv_bfloat16 g_Wgl[2 * G3H * KX_PAD];
__device__ __nv_bfloat16 g_W1h[TWOH * KF_PAD];
__device__ __nv_bfloat16 g_W1l[TWOH * KF_PAD];
__device__ __nv_bfloat16 g_W2h[264 * KF_PAD];
__device__ __nv_bfloat16 g_W2l[264 * KF_PAD];

#define SMEM_SWIZZLE_128B(x) ((x) ^ (((x) >> 3) & 0x70))

__device__ __forceinline__ uint32_t smem_to_u32(const void* p) {
    uint32_t a;
    asm("{ .reg .u64 t; cvta.to.shared.u64 t, %1; cvt.u32.u64 %0, t; }" : "=r"(a) : "l"(p));
    return a;
}

// ---------------- packed f32x2 helpers ----------------
__device__ __forceinline__ ull ffma2(ull a, ull b, ull c) {
    ull d;
    asm("fma.rn.f32x2 %0, %1, %2, %3;" : "=l"(d) : "l"(a), "l"(b), "l"(c));
    return d;
}
__device__ __forceinline__ ull pack2(float lo, float hi) {
    ull d;
    asm("mov.b64 %0, {%1, %2};" : "=l"(d) : "f"(lo), "f"(hi));
    return d;
}
__device__ __forceinline__ float sum2(ull v) {
    float lo, hi;
    asm("mov.b64 {%0, %1}, %2;" : "=f"(lo), "=f"(hi) : "l"(v));
    return lo + hi;
}

// ---------------- warp MMA helpers ----------------
__device__ __forceinline__ void ldsm_x4(uint32_t* r, uint32_t addr) {
    asm volatile("ldmatrix.sync.aligned.m8n8.x4.shared.b16 {%0,%1,%2,%3}, [%4];"
                 : "=r"(r[0]), "=r"(r[1]), "=r"(r[2]), "=r"(r[3]) : "r"(addr));
}
__device__ __forceinline__ void ldsm_x2(uint32_t* r, uint32_t addr) {
    asm volatile("ldmatrix.sync.aligned.m8n8.x2.shared.b16 {%0,%1}, [%2];"
                 : "=r"(r[0]), "=r"(r[1]) : "r"(addr));
}
__device__ __forceinline__ void mma_bf16(float* c, const uint32_t* a, const uint32_t* b) {
    asm volatile("mma.sync.aligned.m16n8k16.row.col.f32.bf16.bf16.f32 "
                 "{%0,%1,%2,%3}, {%4,%5,%6,%7}, {%8,%9}, {%0,%1,%2,%3};"
                 : "+f"(c[0]), "+f"(c[1]), "+f"(c[2]), "+f"(c[3])
                 : "r"(a[0]), "r"(a[1]), "r"(a[2]), "r"(a[3]), "r"(b[0]), "r"(b[1]));
}
__device__ __forceinline__ void cp16(uint32_t saddr, const void* g) {
    asm volatile("cp.async.cg.shared.global [%0], [%1], 16;" :: "r"(saddr), "l"(g));
}
#define CP_COMMIT() asm volatile("cp.async.commit_group;" ::: "memory")
#define CP_WAIT1()  asm volatile("cp.async.wait_group 1;" ::: "memory")

__device__ __forceinline__ void split_bf16(float v, __nv_bfloat16& h, __nv_bfloat16& l) {
    h = __float2bfloat16(v);
    l = __float2bfloat16(v - __bfloat162float(h));
}

// ---------------- conversion kernels ----------------
__global__ void conv_x(const float* __restrict__ x) {
    int idx = blockIdx.x * blockDim.x + threadIdx.x;
    if (idx >= NTOK * KX_PAD) return;
    int row = idx / KX_PAD, col = idx % KX_PAD;
    float v = (col < IN_F) ? x[(size_t)row * IN_F + col] : 0.0f;
    __nv_bfloat16 h, l; split_bf16(v, h, l);
    g_xhi[idx] = h; g_xlo[idx] = l;
}

__global__ void pack_weights(const float* __restrict__ f0W, const float* __restrict__ b0W,
                             const float* __restrict__ k1b, const float* __restrict__ k1s,
                             const float* __restrict__ k1c,
                             const float* __restrict__ k2b, const float* __restrict__ k2s,
                             const float* __restrict__ k2c)
{
    const int NG = 2 * G3H * KX_PAD;
    const int N1 = TWOH * KF_PAD;
    const int N2 = 264 * KF_PAD;
    int idx = blockIdx.x * blockDim.x + threadIdx.x;
    if (idx >= NG + N1 + N2) return;
    float v = 0.0f;
    if (idx < NG) {
        int d = idx / (G3H * KX_PAD), r = (idx / KX_PAD) % G3H, c = idx % KX_PAD;
        if (c < IN_F) v = d ? b0W[r * IN_F + c] : f0W[r * IN_F + c];
        __nv_bfloat16 h, l; split_bf16(v, h, l);
        g_Wgh[idx] = h; g_Wgl[idx] = l;
        return;
    }
    idx -= NG;
    if (idx < N1) {
        int o = idx / KF_PAD, k = idx % KF_PAD;
        if (k < TWOH) v = k1b[o * TWOH + k];
        else if (k < 720) {
            int e = k - TWOH, i = e >> 3, g = e & 7;
            v = k1s[(o * TWOH + i) * 8 + g] * k1c[o * TWOH + i];
        }
        __nv_bfloat16 h, l; split_bf16(v, h, l);
        g_W1h[idx] = h; g_W1l[idx] = l;
        return;
    }
    idx -= N1;
    {
        int o = idx / KF_PAD, k = idx % KF_PAD;
        if (o < IN_F) {
            if (k < TWOH) v = k2b[o * TWOH + k];
            else if (k < 720) {
                int e = k - TWOH, i = e >> 3, g = e & 7;
                v = k2s[(o * TWOH + i) * 8 + g] * k2c[o * TWOH + i];
            }
        }
        __nv_bfloat16 h, l; split_bf16(v, h, l);
        g_W2h[idx] = h; g_W2l[idx] = l;
    }
}

// ---------------- KAN feature expansion ----------------
__device__ __forceinline__ float gridv(int j) { return 0.4f * (float)(j - 3) - 1.0f; }

__device__ __forceinline__ void basis8(float x, float* o) {
    float bset[11];
#pragma unroll
    for (int j = 0; j < 11; j++)
        bset[j] = (x >= gridv(j) && x < gridv(j + 1)) ? 1.0f : 0.0f;
#pragma unroll
    for (int j = 0; j < 10; j++)
        bset[j] = (x - gridv(j)) * 2.5f * bset[j] + (gridv(j + 2) - x) * 2.5f * bset[j + 1];
#pragma unroll
    for (int j = 0; j < 9; j++)
        bset[j] = (x - gridv(j)) * 1.25f * bset[j] + (gridv(j + 3) - x) * 1.25f * bset[j + 1];
#pragma unroll
    for (int j = 0; j < 8; j++)
        o[j] = (x - gridv(j)) * (1.0f / 1.2f) * bset[j] + (gridv(j + 4) - x) * (1.0f / 1.2f) * bset[j + 1];
}

__device__ __forceinline__ void expand_one(int n, int i, float x) {
    float su = x / (1.0f + expf(-x));
    {
        __nv_bfloat16 h, l; split_bf16(su, h, l);
        g_fhi[(size_t)n * KF_PAD + i] = h;
        g_flo[(size_t)n * KF_PAD + i] = l;
    }
    float bs[8];
    basis8(x, bs);
    union { __nv_bfloat16 b[8]; uint4 u; } hv, lv;
#pragma unroll
    for (int j = 0; j < 8; j++) split_bf16(bs[j], hv.b[j], lv.b[j]);
    *(uint4*)&g_fhi[(size_t)n * KF_PAD + TWOH + i * 8] = hv.u;
    *(uint4*)&g_flo[(size_t)n * KF_PAD + TWOH + i * 8] = lv.u;
}

__global__ void expand_feat(const float* __restrict__ X, int total)
{
    int idx = blockIdx.x * blockDim.x + threadIdx.x;
    if (idx >= total) return;
    expand_one(idx / TWOH, idx % TWOH, X[idx]);
}

// ---------------- N-fused HMMA GEMM ----------------
// EPI 1: gates scatter+bias (ny = dir)   EPI 2: kan2 sigmoid
// EPI 3: kan1 -> expand into g_fhi/g_flo directly (rows owned exclusively by CTA)
template <int N_SUB>
struct TM {
    static constexpr int N128   = N_SUB * 128;
    static constexpr int A_ST   = 16384;
    static constexpr int OFF_B  = 32768;
    static constexpr int B_BUF  = 2 * N128;
    static constexpr int TOTAL  = 32768 + 2 * B_BUF;
};

template <int N_SUB, int NCNT, int EPI, int KPAD, int NCHUNK>
__global__ __launch_bounds__(128) void hgemm_multi(
    const __nv_bfloat16* __restrict__ Ahi, const __nv_bfloat16* __restrict__ Alo,
    const __nv_bfloat16* __restrict__ BhiAll, const __nv_bfloat16* __restrict__ BloAll,
    const float* __restrict__ biasF, const float* __restrict__ biasB,
    float* __restrict__ outP, const float* __restrict__ slope)
{
    constexpr int NT8 = N_SUB / 8;
    extern __shared__ __align__(128) char smem[];
    const uint32_t smemB = smem_to_u32(smem);
    const int tid = threadIdx.x, wid = tid >> 5, lid = tid & 31;
    const size_t aRow0 = (size_t)blockIdx.x * 64;

    float acc[NCNT][NT8][4];
#pragma unroll
    for (int y = 0; y < NCNT; y++)
#pragma unroll
        for (int t = 0; t < NT8; t++)
#pragma unroll
            for (int j = 0; j < 4; j++) acc[y][t][j] = 0.0f;

    const int rwA = wid * 16 + (lid & 15);
    const int khA = lid >> 4;
    const int bTs = (lid >> 4) & 1, bKh = (lid >> 3) & 1, bRow = lid & 7;

    auto loadA = [&](int kc, int st) {
        const int kOff = kc << 6;
        const uint32_t base = smemB + st * TM<N_SUB>::A_ST;
#pragma unroll
        for (int j = 0; j < 4; j++) {
            int s = j * 128 + tid;
            int r = s >> 3, c = s & 7;
            size_t go = (aRow0 + r) * (size_t)KPAD + kOff + c * 8;
            uint32_t sw = SMEM_SWIZZLE_128B((uint32_t)(r * 128 + c * 16));
            cp16(base + sw, Ahi + go);
            cp16(base + 8192 + sw, Alo + go);
        }
    };
    auto loadB = [&](int kc, int ny, int nb) {
        const int kOff = kc << 6;
        const __nv_bfloat16* Bhi = BhiAll + (size_t)ny * N_SUB * KPAD;
        const __nv_bfloat16* Blo = BloAll + (size_t)ny * N_SUB * KPAD;
        const uint32_t base = smemB + TM<N_SUB>::OFF_B + nb * TM<N_SUB>::B_BUF;
        for (int s = tid; s < N_SUB * 8; s += 128) {
            int r = s >> 3, c = s & 7;
            size_t go = (size_t)r * KPAD + kOff + c * 8;
            uint32_t sw = SMEM_SWIZZLE_128B((uint32_t)(r * 128 + c * 16));
            cp16(base + sw, Bhi + go);
            cp16(base + TM<N_SUB>::N128 + sw, Blo + go);
        }
    };

    loadA(0, 0);
    loadB(0, 0, 0);
    CP_COMMIT();

    for (int kc = 0; kc < NCHUNK; kc++) {
#pragma unroll
        for (int ny = 0; ny < NCNT; ny++) {
            const int it = kc * NCNT + ny;
            if (it + 1 < NCHUNK * NCNT) {
                int ny2 = (ny + 1 == NCNT) ? 0 : ny + 1;
                int kc2 = (ny + 1 == NCNT) ? kc + 1 : kc;
                if (ny2 == 0) loadA(kc2, kc2 & 1);
                loadB(kc2, ny2, (it + 1) & 1);
            }
            CP_COMMIT();
            CP_WAIT1();
            __syncthreads();

            const uint32_t aBase = smemB + (kc & 1) * TM<N_SUB>::A_ST;
            const uint32_t bBase = smemB + TM<N_SUB>::OFF_B + (it & 1) * TM<N_SUB>::B_BUF;
            const uint32_t aHiB = aBase, aLoB = aBase + 8192;
            const uint32_t bHiB = bBase, bLoB = bBase + TM<N_SUB>::N128;

#pragma unroll
            for (int ks = 0; ks < 4; ks++) {
                uint32_t ah[4], al[4];
                uint32_t offA = SMEM_SWIZZLE_128B((uint32_t)(rwA * 128 + ks * 32 + khA * 16));
                ldsm_x4(ah, aHiB + offA);
                ldsm_x4(al, aLoB + offA);
#pragma unroll
                for (int nt = 0; nt < NT8; nt += 2) {
                    uint32_t bh[4], bl[4];
                    if (nt + 1 < NT8) {
                        int n = (nt + bTs) * 8 + bRow;
                        uint32_t off = SMEM_SWIZZLE_128B((uint32_t)(n * 128 + ks * 32 + bKh * 16));
                        ldsm_x4(bh, bHiB + off);
                        ldsm_x4(bl, bLoB + off);
                    } else {
                        int n = nt * 8 + bRow;
                        uint32_t off = SMEM_SWIZZLE_128B((uint32_t)(n * 128 + ks * 32 + bKh * 16));
                        ldsm_x2(bh, bHiB + off);
                        ldsm_x2(bl, bLoB + off);
                    }
                    mma_bf16(acc[ny][nt], ah, bh);
                    mma_bf16(acc[ny][nt], al, bh);
                    mma_bf16(acc[ny][nt], ah, bl);
                    if (nt + 1 < NT8) {
                        mma_bf16(acc[ny][nt + 1], ah, bh + 2);
                        mma_bf16(acc[ny][nt + 1], al, bh + 2);
                        mma_bf16(acc[ny][nt + 1], ah, bl + 2);
                    }
                }
            }
            __syncthreads();
        }
    }

    // ---- epilogue ----
    const int rr = (int)aRow0 + wid * 16 + (lid >> 2);
    const int cO = 2 * (lid & 3);
    if (EPI == 3) {
        // kan1: expand results straight into feature buffers (rows exclusive to this CTA)
#pragma unroll
        for (int t = 0; t < NT8; t++) {
            int cb = t * 8 + cO;
            expand_one(rr,     cb,     acc[0][t][0]);
            expand_one(rr,     cb + 1, acc[0][t][1]);
            expand_one(rr + 8, cb,     acc[0][t][2]);
            expand_one(rr + 8, cb + 1, acc[0][t][3]);
        }
    } else if (EPI == 1) {
        int b0 = rr / T_STEPS, t0 = rr % T_STEPS;
        int b1 = (rr + 8) / T_STEPS, t1 = (rr + 8) % T_STEPS;
#pragma unroll
        for (int y = 0; y < NCNT; y++) {
            float* baseO = y ? g_giB : g_giF;
            const float* bia = y ? biasB : biasF;
            float* d0 = baseO + ((size_t)t0 * BATCH + b0) * G3H;
            float* d1 = baseO + ((size_t)t1 * BATCH + b1) * G3H;
#pragma unroll
            for (int t = 0; t < NT8; t++) {
                int cb = t * 8 + cO;
                d0[cb]     = acc[y][t][0] + bia[cb];
                d0[cb + 1] = acc[y][t][1] + bia[cb + 1];
                d1[cb]     = acc[y][t][2] + bia[cb];
                d1[cb + 1] = acc[y][t][3] + bia[cb + 1];
            }
        }
    } else {
#pragma unroll
        for (int y = 0; y < NCNT; y++) {
            const int cbase = y * 88;
#pragma unroll
            for (int t = 0; t < NT8; t++) {
                int cb = cbase + t * 8 + cO;
#pragma unroll
                for (int j = 0; j < 2; j++) {
                    int cg = cb + j;
                    if (cg < IN_F) {
                        outP[(size_t)rr * IN_F + cg] =
                            1.2f / (1.0f + expf(-slope[cg] * acc[y][t][j]));
                        outP[(size_t)(rr + 8) * IN_F + cg] =
                            1.2f / (1.0f + expf(-slope[cg] * acc[y][t][2 + j]));
                    }
                }
            }
        }
    }
}

// ---------------- GRU helpers ----------------
__device__ __forceinline__ float sigm_fast(float x) {
    float e = __expf(-x);
    return __fdividef(1.0f, 1.0f + e);
}
__device__ __forceinline__ float tanh_fast(float x) {
    float e = __expf(2.0f * x);
    return 1.0f - __fdividef(2.0f, 1.0f + e);
}

// ---------------- GRU scan (R7 structure + packed f32x2 FMA) ----------------
__global__ __launch_bounds__(320) void gru_scan2(
    const float* __restrict__ WhhF0, const float* __restrict__ bhhF0,
    const float* __restrict__ WihF1, const float* __restrict__ WhhF1,
    const float* __restrict__ bihF1, const float* __restrict__ bhhF1,
    const float* __restrict__ WhhB0, const float* __restrict__ bhhB0,
    const float* __restrict__ WihB1, const float* __restrict__ WhhB1,
    const float* __restrict__ bihB1, const float* __restrict__ bhhB1)
{
    const int b   = blockIdx.x;
    const int dir = blockIdx.y;
    const float* Whh0 = dir ? WhhB0 : WhhF0;
    const float* bhh0 = dir ? bhhB0 : bhhF0;
    const float* W1ih = dir ? WihB1 : WihF1;
    const float* W1hh = dir ? WhhB1 : WhhF1;
    const float* b1ih = dir ? bihB1 : bihF1;
    const float* b1hh = dir ? bhhB1 : bhhF1;
    const float* gi   = dir ? g_giB : g_giF;
    float* out = g_hcat + (size_t)b * T_STEPS * TWOH + dir * HID;

    __shared__ __align__(16) float s_h0[2][HID];
    __shared__ __align__(16) float s_h1[2][HID];

    const int tid = threadIdx.x;
    const bool isA = tid < 160;
    const int lane = isA ? tid : tid - 160;
    const int unit = lane >> 2;
    const int q    = lane & 3;
    const int k0   = q * 10;

    ull wA2[3][5];
    ull wI2[3][5], wH2[3][5];
    float brz0 = 0.f, brz1 = 0.f, bn0 = 0.f;
    float bR = 0.f, bZ = 0.f, bIN = 0.f, bHN = 0.f;
    if (isA) {
#pragma unroll
        for (int g = 0; g < 3; g++)
#pragma unroll
            for (int k = 0; k < 5; k++)
                wA2[g][k] = pack2(Whh0[(g * HID + unit) * HID + k0 + 2 * k],
                                  Whh0[(g * HID + unit) * HID + k0 + 2 * k + 1]);
        brz0 = bhh0[unit];
        brz1 = bhh0[HID + unit];
        bn0  = bhh0[2 * HID + unit];
    } else {
#pragma unroll
        for (int g = 0; g < 3; g++)
#pragma unroll
            for (int k = 0; k < 5; k++) {
                wI2[g][k] = pack2(W1ih[(g * HID + unit) * HID + k0 + 2 * k],
                                  W1ih[(g * HID + unit) * HID + k0 + 2 * k + 1]);
                wH2[g][k] = pack2(W1hh[(g * HID + unit) * HID + k0 + 2 * k],
                                  W1hh[(g * HID + unit) * HID + k0 + 2 * k + 1]);
            }
        bR  = b1ih[unit]           + b1hh[unit];
        bZ  = b1ih[HID + unit]     + b1hh[HID + unit];
        bIN = b1ih[2 * HID + unit];
        bHN = b1hh[2 * HID + unit];
    }

    if (tid < HID) { s_h0[0][tid] = 0.0f; s_h0[1][tid] = 0.0f;
                     s_h1[0][tid] = 0.0f; s_h1[1][tid] = 0.0f; }

    float gc0 = 0.f, gc1 = 0.f, gc2 = 0.f;
    if (isA) {
        int grow = dir ? (T_STEPS - 1) : 0;
        const float* gp = gi + ((size_t)grow * BATCH + b) * G3H;
        gc0 = gp[unit]; gc1 = gp[HID + unit]; gc2 = gp[2 * HID + unit];
    }
    __syncthreads();

    for (int s = 0; s <= T_STEPS; s++) {
        const int cur = s & 1, nxt = (s & 1) ^ 1;
        float gn0 = 0.f, gn1 = 0.f, gn2 = 0.f;

        if (isA) {
            if (s + 1 < T_STEPS) {
                int grow = dir ? (T_STEPS - 2 - s) : (s + 1);
                const float* gp = gi + ((size_t)grow * BATCH + b) * G3H;
                gn0 = gp[unit]; gn1 = gp[HID + unit]; gn2 = gp[2 * HID + unit];
            }
            if (s < T_STEPS) {
                const float* h0c = s_h0[cur];
                const ull* h2 = (const ull*)(h0c + k0);     // 8B aligned (k0*4 % 8 == 0)
                ull hv[5];
#pragma unroll
                for (int k = 0; k < 5; k++) hv[k] = h2[k];
                ull P0 = 0, P1 = 0, P2 = 0;
#pragma unroll
                for (int k = 0; k < 5; k++) {
                    P0 = ffma2(wA2[0][k], hv[k], P0);
                    P1 = ffma2(wA2[1][k], hv[k], P1);
                    P2 = ffma2(wA2[2][k], hv[k], P2);
                }
                float p0 = sum2(P0), p1 = sum2(P1), p2 = sum2(P2);
                p0 += __shfl_xor_sync(0xffffffffu, p0, 1);
                p0 += __shfl_xor_sync(0xffffffffu, p0, 2);
                p1 += __shfl_xor_sync(0xffffffffu, p1, 1);
                p1 += __shfl_xor_sync(0xffffffffu, p1, 2);
                p2 += __shfl_xor_sync(0xffffffffu, p2, 1);
                p2 += __shfl_xor_sync(0xffffffffu, p2, 2);
                float r = sigm_fast(gc0 + p0 + brz0);
                float z = sigm_fast(gc1 + p1 + brz1);
                float n = tanh_fast(gc2 + r * (p2 + bn0));
                float hnew = (1.0f - z) * n + z * h0c[unit];
                if (q == 0) s_h0[nxt][unit] = hnew;
            }
        } else {
            if (s >= 1) {
                const float* h0c = s_h0[cur];
                const float* h1c = s_h1[cur];
                const ull* a2 = (const ull*)(h0c + k0);
                const ull* b2 = (const ull*)(h1c + k0);
                ull av[5], hv[5];
#pragma unroll
                for (int k = 0; k < 5; k++) { av[k] = a2[k]; hv[k] = b2[k]; }
                ull PR = 0, PZ = 0, PIN = 0, PHN = 0;
#pragma unroll
                for (int k = 0; k < 5; k++) {
                    PR  = ffma2(wI2[0][k], av[k], PR);
                    PZ  = ffma2(wI2[1][k], av[k], PZ);
                    PIN = ffma2(wI2[2][k], av[k], PIN);
                    PHN = ffma2(wH2[2][k], hv[k], PHN);
                }
#pragma unroll
                for (int k = 0; k < 5; k++) {
                    PR = ffma2(wH2[0][k], hv[k], PR);
                    PZ = ffma2(wH2[1][k], hv[k], PZ);
                }
                float pr = sum2(PR), pz = sum2(PZ), pin = sum2(PIN), phn = sum2(PHN);
                pr  += __shfl_xor_sync(0xffffffffu, pr, 1);
                pr  += __shfl_xor_sync(0xffffffffu, pr, 2);
                pz  += __shfl_xor_sync(0xffffffffu, pz, 1);
                pz  += __shfl_xor_sync(0xffffffffu, pz, 2);
                pin += __shfl_xor_sync(0xffffffffu, pin, 1);
                pin += __shfl_xor_sync(0xffffffffu, pin, 2);
                phn += __shfl_xor_sync(0xffffffffu, phn, 1);
                phn += __shfl_xor_sync(0xffffffffu, phn, 2);
                float r = sigm_fast(pr + bR);
                float z = sigm_fast(pz + bZ);
                float n = tanh_fast(pin + bIN + r * (phn + bHN));
                float h = (1.0f - z) * n + z * h1c[unit];
                if (q == 0) {
                    s_h1[nxt][unit] = h;
                    out[(size_t)(s - 1) * TWOH + unit] = h;
                }
            }
        }
        __syncthreads();
        gc0 = gn0; gc1 = gn1; gc2 = gn2;
    }
}

// ---------------- launch ----------------
extern "C" void kernel_launch(void* const* d_in, const int* in_sizes, int n_in,
                              void* d_out, int out_size)
{
    const float* x     = (const float*)d_in[0];
    const float* f0Wih = (const float*)d_in[2];
    const float* f0Whh = (const float*)d_in[3];
    const float* f0bih = (const float*)d_in[4];
    const float* f0bhh = (const float*)d_in[5];
    const float* f1Wih = (const float*)d_in[6];
    const float* f1Whh = (const float*)d_in[7];
    const float* f1bih = (const float*)d_in[8];
    const float* f1bhh = (const float*)d_in[9];
    const float* b0Wih = (const float*)d_in[10];
    const float* b0Whh = (const float*)d_in[11];
    const float* b0bih = (const float*)d_in[12];
    const float* b0bhh = (const float*)d_in[13];
    const float* b1Wih = (const float*)d_in[14];
    const float* b1Whh = (const float*)d_in[15];
    const float* b1bih = (const float*)d_in[16];
    const float* b1bhh = (const float*)d_in[17];
    const float* k1b   = (const float*)d_in[18];
    const float* k1s   = (const float*)d_in[19];
    const float* k1c   = (const float*)d_in[20];
    const float* k2b   = (const float*)d_in[21];
    const float* k2s   = (const float*)d_in[22];
    const float* k2c   = (const float*)d_in[23];
    const float* slope = (const float*)d_in[24];
    float* out = (float*)d_out;

    __nv_bfloat16 *p_xhi, *p_xlo, *p_fhi, *p_flo, *p_Wgh, *p_Wgl, *p_W1h, *p_W1l, *p_W2h, *p_W2l;
    float *p_hcat;
    cudaGetSymbolAddress((void**)&p_xhi, g_xhi);
    cudaGetSymbolAddress((void**)&p_xlo, g_xlo);
    cudaGetSymbolAddress((void**)&p_fhi, g_fhi);
    cudaGetSymbolAddress((void**)&p_flo, g_flo);
    cudaGetSymbolAddress((void**)&p_Wgh, g_Wgh);
    cudaGetSymbolAddress((void**)&p_Wgl, g_Wgl);
    cudaGetSymbolAddress((void**)&p_W1h, g_W1h);
    cudaGetSymbolAddress((void**)&p_W1l, g_W1l);
    cudaGetSymbolAddress((void**)&p_W2h, g_W2h);
    cudaGetSymbolAddress((void**)&p_W2l, g_W2l);
    cudaGetSymbolAddress((void**)&p_hcat, g_hcat);

    cudaFuncSetAttribute((const void*)hgemm_multi<120, 2, 1, KX_PAD, 5>,
                         cudaFuncAttributeMaxDynamicSharedMemorySize, TM<120>::TOTAL);
    cudaFuncSetAttribute((const void*)hgemm_multi<80, 1, 3, KF_PAD, 12>,
                         cudaFuncAttributeMaxDynamicSharedMemorySize, TM<80>::TOTAL);
    cudaFuncSetAttribute((const void*)hgemm_multi<88, 3, 2, KF_PAD, 12>,
                         cudaFuncAttributeMaxDynamicSharedMemorySize, TM<88>::TOTAL);

    // 1. conversions
    conv_x<<<(NTOK * KX_PAD + 255) / 256, 256>>>(x);
    {
        int total = 2 * G3H * KX_PAD + TWOH * KF_PAD + 264 * KF_PAD;
        pack_weights<<<(total + 255) / 256, 256>>>(f0Wih, b0Wih, k1b, k1s, k1c, k2b, k2s, k2c);
    }
    // 2. layer-0 input gates: both dirs fused (A loaded once)
    {
        hgemm_multi<120, 2, 1, KX_PAD, 5><<<NTOK / 64, 128, TM<120>::TOTAL>>>(
            p_xhi, p_xlo, p_Wgh, p_Wgl, f0bih, b0bih, nullptr, nullptr);
    }
    // 3. GRU scan (f32x2 packed FMA)
    {
        dim3 grid(BATCH, 2);
        gru_scan2<<<grid, 320>>>(f0Whh, f0bhh, f1Wih, f1Whh, f1bih, f1bhh,
                                 b0Whh, b0bhh, b1Wih, b1Whh, b1bih, b1bhh);
    }
    // 4. KAN layer 1: expand(hcat) + GEMM with fused expand-epilogue (no y1 roundtrip)
    {
        expand_feat<<<(NTOK * TWOH + 255) / 256, 256>>>(p_hcat, NTOK * TWOH);
        hgemm_multi<80, 1, 3, KF_PAD, 12><<<NTOK / 64, 128, TM<80>::TOTAL>>>(
            p_fhi, p_flo, p_W1h, p_W1l, nullptr, nullptr, nullptr, nullptr);
    }
    // 5. KAN layer 2: N-fused GEMM + sigmoid (reads features written by kan1 epilogue)
    {
        hgemm_multi<88, 3, 2, KF_PAD, 12><<<NTOK / 64, 128, TM<88>::TOTAL>>>(
            p_fhi, p_flo, p_W2h, p_W2l, nullptr, nullptr, out, slope);
    }
    (void)in_sizes; (void)n_in; (void)out_size;
}